// round 3
// baseline (speedup 1.0000x reference)
#include <cuda_runtime.h>

// D = 16777216 floats per vector; n4 = D/4 float4 elements.
// Output: out[0..D) = x, out[D..D+6) = {ly0·x, ly1·x, ly1·ly0, ly2·x, ly2·ly0, ly2·ly1}
//
// Single-kernel design: each block writes 6 partial sums to __device__ scratch;
// the last block to arrive (atomic ticket + threadfence) reduces all partials
// deterministically and writes the 6-float tail. Counter self-resets -> graph-safe.
//
// R2 lesson: __stcs on the x-copy store dropped HBM 6.6->5.6 TB/s. Plain STG only.

#define NBLOCKS 4096
#define NTHREADS 256

__device__ float g_partials[6][NBLOCKS];
__device__ unsigned int g_ticket = 0;

__global__ void __launch_bounds__(NTHREADS)
dlrm_fused_kernel(const float4* __restrict__ xv,
                  const float4* __restrict__ l0v,
                  const float4* __restrict__ l1v,
                  const float4* __restrict__ l2v,
                  float4* __restrict__ outx,
                  float* __restrict__ out_tail,
                  int n4) {
    float s0 = 0.f, s1 = 0.f, s2 = 0.f, s3 = 0.f, s4 = 0.f, s5 = 0.f;

    const int stride = gridDim.x * blockDim.x;
    for (int i = blockIdx.x * blockDim.x + threadIdx.x; i < n4; i += stride) {
        const float4 a = xv[i];
        const float4 b = l0v[i];
        const float4 c = l1v[i];
        const float4 d = l2v[i];
        outx[i] = a;  // fused copy of x into out (plain store — see R2 lesson)

        s0 += b.x * a.x + b.y * a.y + b.z * a.z + b.w * a.w;  // ly0 · x
        s1 += c.x * a.x + c.y * a.y + c.z * a.z + c.w * a.w;  // ly1 · x
        s2 += c.x * b.x + c.y * b.y + c.z * b.z + c.w * b.w;  // ly1 · ly0
        s3 += d.x * a.x + d.y * a.y + d.z * a.z + d.w * a.w;  // ly2 · x
        s4 += d.x * b.x + d.y * b.y + d.z * b.z + d.w * b.w;  // ly2 · ly0
        s5 += d.x * c.x + d.y * c.y + d.z * c.z + d.w * c.w;  // ly2 · ly1
    }

    // Warp-level reduction
    #pragma unroll
    for (int off = 16; off > 0; off >>= 1) {
        s0 += __shfl_down_sync(0xFFFFFFFFu, s0, off);
        s1 += __shfl_down_sync(0xFFFFFFFFu, s1, off);
        s2 += __shfl_down_sync(0xFFFFFFFFu, s2, off);
        s3 += __shfl_down_sync(0xFFFFFFFFu, s3, off);
        s4 += __shfl_down_sync(0xFFFFFFFFu, s4, off);
        s5 += __shfl_down_sync(0xFFFFFFFFu, s5, off);
    }

    __shared__ float smem[6][NTHREADS / 32];
    __shared__ bool s_is_last;
    const int warp = threadIdx.x >> 5;
    const int lane = threadIdx.x & 31;
    if (lane == 0) {
        smem[0][warp] = s0; smem[1][warp] = s1; smem[2][warp] = s2;
        smem[3][warp] = s3; smem[4][warp] = s4; smem[5][warp] = s5;
    }
    __syncthreads();

    // Threads 0..5 write this block's 6 partials to global scratch.
    if (threadIdx.x < 6) {
        float v = 0.f;
        #pragma unroll
        for (int w = 0; w < NTHREADS / 32; w++) v += smem[threadIdx.x][w];
        g_partials[threadIdx.x][blockIdx.x] = v;
    }
    __threadfence();  // make partials visible before taking the ticket
    __syncthreads();

    if (threadIdx.x == 0) {
        unsigned int t = atomicAdd(&g_ticket, 1u);
        s_is_last = (t == gridDim.x - 1);
    }
    __syncthreads();
    if (!s_is_last) return;

    // Last block: deterministic reduction of all NBLOCKS partials per product.
    const int nb = gridDim.x;
    #pragma unroll
    for (int p = 0; p < 6; p++) {
        float v = 0.f;
        for (int j = threadIdx.x; j < nb; j += NTHREADS) v += g_partials[p][j];
        #pragma unroll
        for (int off = 16; off > 0; off >>= 1)
            v += __shfl_down_sync(0xFFFFFFFFu, v, off);
        if (lane == 0) smem[p][warp] = v;
    }
    __syncthreads();
    if (threadIdx.x < 6) {
        float v = 0.f;
        #pragma unroll
        for (int w = 0; w < NTHREADS / 32; w++) v += smem[threadIdx.x][w];
        out_tail[threadIdx.x] = v;
    }
    if (threadIdx.x == 0) g_ticket = 0;  // reset for next graph replay
}

extern "C" void kernel_launch(void* const* d_in, const int* in_sizes, int n_in,
                              void* d_out, int out_size) {
    const float* x  = (const float*)d_in[0];
    const float* l0 = (const float*)d_in[1];
    const float* l1 = (const float*)d_in[2];
    const float* l2 = (const float*)d_in[3];
    float* out = (float*)d_out;

    const int D  = in_sizes[0];   // 16777216
    const int n4 = D / 4;         // 4194304

    int blocks = NBLOCKS;
    const int maxBlocks = (n4 + NTHREADS - 1) / NTHREADS;
    if (blocks > maxBlocks) blocks = maxBlocks;

    dlrm_fused_kernel<<<blocks, NTHREADS>>>(
        (const float4*)x, (const float4*)l0, (const float4*)l1, (const float4*)l2,
        (float4*)out, out + D, n4);
}

// round 4
// speedup vs baseline: 1.0043x; 1.0043x over previous
#include <cuda_runtime.h>

// D = 16777216 floats per vector; n4 = D/4 float4 elements.
// Output: out[0..D) = x, out[D..D+6) = {ly0·x, ly1·x, ly1·ly0, ly2·x, ly2·ly0, ly2·ly1}
//
// Single kernel. Each block's thread 0 writes 6 partials to __device__ scratch,
// issues ONE gpu-scope fence, takes a ticket; the last block reduces all
// partials deterministically and writes the 6-float tail. Ticket self-resets.
//
// R2/R3 lesson: __threadfence() executed by ALL threads emits per-thread
// CCTL.IVALL (L1D flush) on sm_103a -> cost ~8.7us. Fence from thread 0 only.

#define NBLOCKS 4096
#define NTHREADS 256

__device__ float g_partials[6][NBLOCKS];
__device__ unsigned int g_ticket = 0;

__global__ void __launch_bounds__(NTHREADS)
dlrm_fused_kernel(const float4* __restrict__ xv,
                  const float4* __restrict__ l0v,
                  const float4* __restrict__ l1v,
                  const float4* __restrict__ l2v,
                  float4* __restrict__ outx,
                  float* __restrict__ out_tail,
                  int n4) {
    float s0 = 0.f, s1 = 0.f, s2 = 0.f, s3 = 0.f, s4 = 0.f, s5 = 0.f;

    const int stride = gridDim.x * blockDim.x;
    for (int i = blockIdx.x * blockDim.x + threadIdx.x; i < n4; i += stride) {
        const float4 a = xv[i];
        const float4 b = l0v[i];
        const float4 c = l1v[i];
        const float4 d = l2v[i];
        outx[i] = a;  // fused copy of x into out

        s0 += b.x * a.x + b.y * a.y + b.z * a.z + b.w * a.w;  // ly0 · x
        s1 += c.x * a.x + c.y * a.y + c.z * a.z + c.w * a.w;  // ly1 · x
        s2 += c.x * b.x + c.y * b.y + c.z * b.z + c.w * b.w;  // ly1 · ly0
        s3 += d.x * a.x + d.y * a.y + d.z * a.z + d.w * a.w;  // ly2 · x
        s4 += d.x * b.x + d.y * b.y + d.z * b.z + d.w * b.w;  // ly2 · ly0
        s5 += d.x * c.x + d.y * c.y + d.z * c.z + d.w * c.w;  // ly2 · ly1
    }

    // Warp-level reduction
    #pragma unroll
    for (int off = 16; off > 0; off >>= 1) {
        s0 += __shfl_down_sync(0xFFFFFFFFu, s0, off);
        s1 += __shfl_down_sync(0xFFFFFFFFu, s1, off);
        s2 += __shfl_down_sync(0xFFFFFFFFu, s2, off);
        s3 += __shfl_down_sync(0xFFFFFFFFu, s3, off);
        s4 += __shfl_down_sync(0xFFFFFFFFu, s4, off);
        s5 += __shfl_down_sync(0xFFFFFFFFu, s5, off);
    }

    __shared__ float smem[6][NTHREADS / 32];
    __shared__ bool s_is_last;
    const int warp = threadIdx.x >> 5;
    const int lane = threadIdx.x & 31;
    if (lane == 0) {
        smem[0][warp] = s0; smem[1][warp] = s1; smem[2][warp] = s2;
        smem[3][warp] = s3; smem[4][warp] = s4; smem[5][warp] = s5;
    }
    __syncthreads();

    // Thread 0 ONLY: combine warps, publish partials, fence once, take ticket.
    if (threadIdx.x == 0) {
        #pragma unroll
        for (int p = 0; p < 6; p++) {
            float v = 0.f;
            #pragma unroll
            for (int w = 0; w < NTHREADS / 32; w++) v += smem[p][w];
            g_partials[p][blockIdx.x] = v;
        }
        __threadfence();  // one fence per block, not per thread
        unsigned int t = atomicAdd(&g_ticket, 1u);
        s_is_last = (t == gridDim.x - 1);
    }
    __syncthreads();
    if (!s_is_last) return;

    // Last block: deterministic reduction of all NBLOCKS partials per product.
    const int nb = gridDim.x;
    #pragma unroll
    for (int p = 0; p < 6; p++) {
        float v = 0.f;
        for (int j = threadIdx.x; j < nb; j += NTHREADS) v += g_partials[p][j];
        #pragma unroll
        for (int off = 16; off > 0; off >>= 1)
            v += __shfl_down_sync(0xFFFFFFFFu, v, off);
        if (lane == 0) smem[p][warp] = v;
    }
    __syncthreads();
    if (threadIdx.x < 6) {
        float v = 0.f;
        #pragma unroll
        for (int w = 0; w < NTHREADS / 32; w++) v += smem[threadIdx.x][w];
        out_tail[threadIdx.x] = v;
    }
    if (threadIdx.x == 0) g_ticket = 0;  // reset for next graph replay
}

extern "C" void kernel_launch(void* const* d_in, const int* in_sizes, int n_in,
                              void* d_out, int out_size) {
    const float* x  = (const float*)d_in[0];
    const float* l0 = (const float*)d_in[1];
    const float* l1 = (const float*)d_in[2];
    const float* l2 = (const float*)d_in[3];
    float* out = (float*)d_out;

    const int D  = in_sizes[0];   // 16777216
    const int n4 = D / 4;         // 4194304

    int blocks = NBLOCKS;
    const int maxBlocks = (n4 + NTHREADS - 1) / NTHREADS;
    if (blocks > maxBlocks) blocks = maxBlocks;

    dlrm_fused_kernel<<<blocks, NTHREADS>>>(
        (const float4*)x, (const float4*)l0, (const float4*)l1, (const float4*)l2,
        (float4*)out, out + D, n4);
}

// round 5
// speedup vs baseline: 1.0509x; 1.0464x over previous
#include <cuda_runtime.h>

// D = 16777216 floats per vector; n4 = D/4 float4 elements.
// Output: out[0..D) = x, out[D..D+6) = {ly0·x, ly1·x, ly1·ly0, ly2·x, ly2·ly0, ly2·ly1}
//
// R4 post-mortem: the last-block reduction over 6x4096 global partials was a
// ~8us serialized DRAM-latency tail (partials evicted from L2 by the 320MB
// stream). Fix: accumulate via atomicAdd into 6 device-global floats (proven
// free in R1), last block just atomicExch-reads them into out_tail and resets.

#define NTHREADS 256
#define NBLOCKS 4096

__device__ float g_acc[6];            // zero-initialized; self-resetting each run
__device__ unsigned int g_ticket = 0; // self-resetting

#define DOT4(u, v) ((u).x*(v).x + (u).y*(v).y + (u).z*(v).z + (u).w*(v).w)

__global__ void __launch_bounds__(NTHREADS)
dlrm_fused_kernel(const float4* __restrict__ xv,
                  const float4* __restrict__ l0v,
                  const float4* __restrict__ l1v,
                  const float4* __restrict__ l2v,
                  float4* __restrict__ outx,
                  float* __restrict__ out_tail,
                  int n4) {
    float s0 = 0.f, s1 = 0.f, s2 = 0.f, s3 = 0.f, s4 = 0.f, s5 = 0.f;

    const int stride = gridDim.x * blockDim.x;
    const int i0 = blockIdx.x * blockDim.x + threadIdx.x;

    if (n4 == 4 * stride) {
        // Specialized branchless path: exactly 4 strided positions per thread,
        // processed as 2 x (2 positions with 8 front-batched LDG.128).
        #pragma unroll
        for (int k = 0; k < 2; k++) {
            const int i = i0 + (2 * k) * stride;
            const int j = i + stride;
            const float4 a0 = xv[i],  b0 = l0v[i], c0 = l1v[i], d0 = l2v[i];
            const float4 a1 = xv[j],  b1 = l0v[j], c1 = l1v[j], d1 = l2v[j];
            outx[i] = a0;
            outx[j] = a1;
            s0 += DOT4(b0, a0) + DOT4(b1, a1);
            s1 += DOT4(c0, a0) + DOT4(c1, a1);
            s2 += DOT4(c0, b0) + DOT4(c1, b1);
            s3 += DOT4(d0, a0) + DOT4(d1, a1);
            s4 += DOT4(d0, b0) + DOT4(d1, b1);
            s5 += DOT4(d0, c0) + DOT4(d1, c1);
        }
    } else {
        // Generic fallback (any n4)
        for (int i = i0; i < n4; i += stride) {
            const float4 a = xv[i];
            const float4 b = l0v[i];
            const float4 c = l1v[i];
            const float4 d = l2v[i];
            outx[i] = a;
            s0 += DOT4(b, a);
            s1 += DOT4(c, a);
            s2 += DOT4(c, b);
            s3 += DOT4(d, a);
            s4 += DOT4(d, b);
            s5 += DOT4(d, c);
        }
    }

    // Warp-level reduction
    #pragma unroll
    for (int off = 16; off > 0; off >>= 1) {
        s0 += __shfl_down_sync(0xFFFFFFFFu, s0, off);
        s1 += __shfl_down_sync(0xFFFFFFFFu, s1, off);
        s2 += __shfl_down_sync(0xFFFFFFFFu, s2, off);
        s3 += __shfl_down_sync(0xFFFFFFFFu, s3, off);
        s4 += __shfl_down_sync(0xFFFFFFFFu, s4, off);
        s5 += __shfl_down_sync(0xFFFFFFFFu, s5, off);
    }

    __shared__ float smem[6][NTHREADS / 32];
    __shared__ bool s_is_last;
    const int warp = threadIdx.x >> 5;
    const int lane = threadIdx.x & 31;
    if (lane == 0) {
        smem[0][warp] = s0; smem[1][warp] = s1; smem[2][warp] = s2;
        smem[3][warp] = s3; smem[4][warp] = s4; smem[5][warp] = s5;
    }
    __syncthreads();

    // Threads 0..5: one atomicAdd each into the 6 global accumulators
    // (R1 proved this pattern costs ~nothing). Thread 0 then fences + tickets.
    if (threadIdx.x < 6) {
        float v = 0.f;
        #pragma unroll
        for (int w = 0; w < NTHREADS / 32; w++) v += smem[threadIdx.x][w];
        atomicAdd(&g_acc[threadIdx.x], v);
    }
    __syncthreads();   // ensure all 6 atomics of this block were issued
    if (threadIdx.x == 0) {
        __threadfence();  // order this block's g_acc adds before its ticket
        unsigned int t = atomicAdd(&g_ticket, 1u);
        s_is_last = (t == gridDim.x - 1);
    }
    __syncthreads();

    if (s_is_last) {
        // All blocks' adds are visible (ticket order + fences). Read+reset in one atomic.
        if (threadIdx.x < 6)
            out_tail[threadIdx.x] = atomicExch(&g_acc[threadIdx.x], 0.0f);
        if (threadIdx.x == 0)
            atomicExch(&g_ticket, 0u);  // reset for next graph replay
    }
}

extern "C" void kernel_launch(void* const* d_in, const int* in_sizes, int n_in,
                              void* d_out, int out_size) {
    const float* x  = (const float*)d_in[0];
    const float* l0 = (const float*)d_in[1];
    const float* l1 = (const float*)d_in[2];
    const float* l2 = (const float*)d_in[3];
    float* out = (float*)d_out;

    const int D  = in_sizes[0];   // 16777216
    const int n4 = D / 4;         // 4194304

    int blocks = NBLOCKS;
    const int maxBlocks = (n4 + NTHREADS - 1) / NTHREADS;
    if (blocks > maxBlocks) blocks = maxBlocks;

    dlrm_fused_kernel<<<blocks, NTHREADS>>>(
        (const float4*)x, (const float4*)l0, (const float4*)l1, (const float4*)l2,
        (float4*)out, out + D, n4);
}

// round 6
// speedup vs baseline: 1.0848x; 1.0323x over previous
#include <cuda_runtime.h>

// D = 16777216 floats per vector; n4 = D/4 float4 elements.
// Output: out[0..D) = x, out[D..D+6) = {ly0·x, ly1·x, ly1·ly0, ly2·x, ly2·ly0, ly2·ly1}
//
// Lessons so far:
//  R2/R3: cache hints + per-thread fences: red herrings.
//  R4: last-block global-partial reduce = ~8us serialized DRAM tail. Use atomics.
//  R5: x2 unroll -> regs 54, occ 47%, DRAM stuck 76%. MLP must come from
//      occupancy, not unrolling. Keep the simple R1 loop body (regs 32, occ 92%).
//  R6: single-wave launch (152 SMs x 8 blocks = 1216 blocks) to avoid wave
//      transitions; grid-stride covers ~13.5 iters/thread.

#define NTHREADS 256
#define NBLOCKS  (152 * 8)   // one full wave on GB300 (152 SMs, 8 blocks/SM)

__device__ float g_acc[6];            // zero-initialized; self-resetting each run
__device__ unsigned int g_ticket = 0; // self-resetting

#define DOT4(u, v) ((u).x*(v).x + (u).y*(v).y + (u).z*(v).z + (u).w*(v).w)

__global__ void __launch_bounds__(NTHREADS, 8)
dlrm_fused_kernel(const float4* __restrict__ xv,
                  const float4* __restrict__ l0v,
                  const float4* __restrict__ l1v,
                  const float4* __restrict__ l2v,
                  float4* __restrict__ outx,
                  float* __restrict__ out_tail,
                  int n4) {
    float s0 = 0.f, s1 = 0.f, s2 = 0.f, s3 = 0.f, s4 = 0.f, s5 = 0.f;

    const int stride = gridDim.x * blockDim.x;
    for (int i = blockIdx.x * blockDim.x + threadIdx.x; i < n4; i += stride) {
        const float4 a = xv[i];
        const float4 b = l0v[i];
        const float4 c = l1v[i];
        const float4 d = l2v[i];
        outx[i] = a;  // fused copy of x into out

        s0 += DOT4(b, a);  // ly0 · x
        s1 += DOT4(c, a);  // ly1 · x
        s2 += DOT4(c, b);  // ly1 · ly0
        s3 += DOT4(d, a);  // ly2 · x
        s4 += DOT4(d, b);  // ly2 · ly0
        s5 += DOT4(d, c);  // ly2 · ly1
    }

    // Warp-level reduction
    #pragma unroll
    for (int off = 16; off > 0; off >>= 1) {
        s0 += __shfl_down_sync(0xFFFFFFFFu, s0, off);
        s1 += __shfl_down_sync(0xFFFFFFFFu, s1, off);
        s2 += __shfl_down_sync(0xFFFFFFFFu, s2, off);
        s3 += __shfl_down_sync(0xFFFFFFFFu, s3, off);
        s4 += __shfl_down_sync(0xFFFFFFFFu, s4, off);
        s5 += __shfl_down_sync(0xFFFFFFFFu, s5, off);
    }

    __shared__ float smem[6][NTHREADS / 32];
    __shared__ bool s_is_last;
    const int warp = threadIdx.x >> 5;
    const int lane = threadIdx.x & 31;
    if (lane == 0) {
        smem[0][warp] = s0; smem[1][warp] = s1; smem[2][warp] = s2;
        smem[3][warp] = s3; smem[4][warp] = s4; smem[5][warp] = s5;
    }
    __syncthreads();

    // Threads 0..5: one atomicAdd each into the 6 global accumulators.
    if (threadIdx.x < 6) {
        float v = 0.f;
        #pragma unroll
        for (int w = 0; w < NTHREADS / 32; w++) v += smem[threadIdx.x][w];
        atomicAdd(&g_acc[threadIdx.x], v);
    }
    __syncthreads();   // all 6 atomics of this block issued
    if (threadIdx.x == 0) {
        __threadfence();  // order this block's g_acc adds before its ticket
        unsigned int t = atomicAdd(&g_ticket, 1u);
        s_is_last = (t == gridDim.x - 1);
    }
    __syncthreads();

    if (s_is_last) {
        // All blocks' adds visible (ticket order + fences). Read+reset in one atomic.
        if (threadIdx.x < 6)
            out_tail[threadIdx.x] = atomicExch(&g_acc[threadIdx.x], 0.0f);
        if (threadIdx.x == 0)
            atomicExch(&g_ticket, 0u);  // reset for next graph replay
    }
}

extern "C" void kernel_launch(void* const* d_in, const int* in_sizes, int n_in,
                              void* d_out, int out_size) {
    const float* x  = (const float*)d_in[0];
    const float* l0 = (const float*)d_in[1];
    const float* l1 = (const float*)d_in[2];
    const float* l2 = (const float*)d_in[3];
    float* out = (float*)d_out;

    const int D  = in_sizes[0];   // 16777216
    const int n4 = D / 4;         // 4194304

    int blocks = NBLOCKS;
    const int maxBlocks = (n4 + NTHREADS - 1) / NTHREADS;
    if (blocks > maxBlocks) blocks = maxBlocks;

    dlrm_fused_kernel<<<blocks, NTHREADS>>>(
        (const float4*)x, (const float4*)l0, (const float4*)l1, (const float4*)l2,
        (float4*)out, out + D, n4);
}

// round 7
// speedup vs baseline: 1.1144x; 1.0273x over previous
#include <cuda_runtime.h>

// D = 16777216 floats per vector; n4 = D/4 float4 elements.
// Output: out[0..D) = x, out[D..D+6) = {ly0·x, ly1·x, ly1·ly0, ly2·x, ly2·ly0, ly2·ly1}
//
// Lessons:
//  R2/R3: cache hints / per-thread fences: red herrings.
//  R4: last-block reduce over global partials = serialized DRAM tail. Atomics win.
//  R5: unroll -> regs 54, occ 47%. Keep simple loop (regs 32).
//  R6: single-wave (1216 blks) slower than R1's 4096 blks. Restore 4096.
//  R7: remove __threadfence (CCTL.IVALL L1D flush) entirely. Ordering comes from
//      consuming atomicAdd return values (atomic performed at L2 before the
//      dependent STS issues) + __syncthreads + ticket atomic. Fence-free.

#define NTHREADS 256
#define NBLOCKS  4096

__device__ float g_acc[6];            // zero-init; self-resetting each run
__device__ unsigned int g_ticket = 0; // self-resetting

#define DOT4(u, v) ((u).x*(v).x + (u).y*(v).y + (u).z*(v).z + (u).w*(v).w)

__global__ void __launch_bounds__(NTHREADS)
dlrm_fused_kernel(const float4* __restrict__ xv,
                  const float4* __restrict__ l0v,
                  const float4* __restrict__ l1v,
                  const float4* __restrict__ l2v,
                  float4* __restrict__ outx,
                  float* __restrict__ out_tail,
                  int n4) {
    float s0 = 0.f, s1 = 0.f, s2 = 0.f, s3 = 0.f, s4 = 0.f, s5 = 0.f;

    const int stride = gridDim.x * blockDim.x;
    for (int i = blockIdx.x * blockDim.x + threadIdx.x; i < n4; i += stride) {
        const float4 a = xv[i];
        const float4 b = l0v[i];
        const float4 c = l1v[i];
        const float4 d = l2v[i];
        outx[i] = a;  // fused copy of x into out

        s0 += DOT4(b, a);  // ly0 · x
        s1 += DOT4(c, a);  // ly1 · x
        s2 += DOT4(c, b);  // ly1 · ly0
        s3 += DOT4(d, a);  // ly2 · x
        s4 += DOT4(d, b);  // ly2 · ly0
        s5 += DOT4(d, c);  // ly2 · ly1
    }

    // Warp-level reduction
    #pragma unroll
    for (int off = 16; off > 0; off >>= 1) {
        s0 += __shfl_down_sync(0xFFFFFFFFu, s0, off);
        s1 += __shfl_down_sync(0xFFFFFFFFu, s1, off);
        s2 += __shfl_down_sync(0xFFFFFFFFu, s2, off);
        s3 += __shfl_down_sync(0xFFFFFFFFu, s3, off);
        s4 += __shfl_down_sync(0xFFFFFFFFu, s4, off);
        s5 += __shfl_down_sync(0xFFFFFFFFu, s5, off);
    }

    __shared__ float smem[6][NTHREADS / 32];
    __shared__ bool s_is_last;
    volatile __shared__ float s_old[6];  // forces atomic round-trip completion
    const int warp = threadIdx.x >> 5;
    const int lane = threadIdx.x & 31;
    if (lane == 0) {
        smem[0][warp] = s0; smem[1][warp] = s1; smem[2][warp] = s2;
        smem[3][warp] = s3; smem[4][warp] = s4; smem[5][warp] = s5;
    }
    __syncthreads();

    // Threads 0..5: atomicAdd into global accumulators; CONSUME the return
    // value so the atomic is performed at L2 before we pass the barrier.
    if (threadIdx.x < 6) {
        float v = 0.f;
        #pragma unroll
        for (int w = 0; w < NTHREADS / 32; w++) v += smem[threadIdx.x][w];
        float old = atomicAdd(&g_acc[threadIdx.x], v);
        s_old[threadIdx.x] = old;  // volatile STS: depends on atomic result
    }
    __syncthreads();  // drains STS; all 6 adds performed at L2 before ticket

    if (threadIdx.x == 0) {
        unsigned int t = atomicAdd(&g_ticket, 1u);
        s_is_last = (t == gridDim.x - 1);
    }
    __syncthreads();

    if (s_is_last) {
        // Every block's adds were performed at L2 before its ticket; we saw
        // the final ticket, so g_acc is complete. Read + reset atomically.
        if (threadIdx.x < 6)
            out_tail[threadIdx.x] = atomicExch(&g_acc[threadIdx.x], 0.0f);
        if (threadIdx.x == 0)
            atomicExch(&g_ticket, 0u);  // reset for next graph replay
    }
}

extern "C" void kernel_launch(void* const* d_in, const int* in_sizes, int n_in,
                              void* d_out, int out_size) {
    const float* x  = (const float*)d_in[0];
    const float* l0 = (const float*)d_in[1];
    const float* l1 = (const float*)d_in[2];
    const float* l2 = (const float*)d_in[3];
    float* out = (float*)d_out;

    const int D  = in_sizes[0];   // 16777216
    const int n4 = D / 4;         // 4194304

    int blocks = NBLOCKS;
    const int maxBlocks = (n4 + NTHREADS - 1) / NTHREADS;
    if (blocks > maxBlocks) blocks = maxBlocks;

    dlrm_fused_kernel<<<blocks, NTHREADS>>>(
        (const float4*)x, (const float4*)l0, (const float4*)l1, (const float4*)l2,
        (float4*)out, out + D, n4);
}

// round 8
// speedup vs baseline: 1.1244x; 1.0090x over previous
#include <cuda_runtime.h>

// D = 16777216 floats per vector; n4 = D/4 float4 elements.
// Output: out[0..D) = x, out[D..D+6) = {ly0·x, ly1·x, ly1·ly0, ly2·x, ly2·ly0, ly2·ly1}
//
// Lessons:
//  R4: last-block global-partial reduce = serialized DRAM tail. Atomics win.
//  R5: unroll -> regs 54, occ 47%. Keep simple loop (regs 32).
//  R6: single-wave 1216 blks slower than 4096. Keep 4096.
//  R7: __threadfence (CCTL.IVALL) was the ~3us epilogue tax. Fence-free ordering
//      via consumed atomicAdd return + syncthreads + ticket. CONFIRMED.
//  R8: re-test streaming hints with the fixed epilogue: R2-vs-R3 showed .cs store
//      was +0.6us even under the bad epilogue. Zero-reuse streams -> __ldcs/__stcs.

#define NTHREADS 256
#define NBLOCKS  4096

__device__ float g_acc[6];            // zero-init; self-resetting each run
__device__ unsigned int g_ticket = 0; // self-resetting

#define DOT4(u, v) ((u).x*(v).x + (u).y*(v).y + (u).z*(v).z + (u).w*(v).w)

__global__ void __launch_bounds__(NTHREADS)
dlrm_fused_kernel(const float4* __restrict__ xv,
                  const float4* __restrict__ l0v,
                  const float4* __restrict__ l1v,
                  const float4* __restrict__ l2v,
                  float4* __restrict__ outx,
                  float* __restrict__ out_tail,
                  int n4) {
    float s0 = 0.f, s1 = 0.f, s2 = 0.f, s3 = 0.f, s4 = 0.f, s5 = 0.f;

    const int stride = gridDim.x * blockDim.x;
    for (int i = blockIdx.x * blockDim.x + threadIdx.x; i < n4; i += stride) {
        const float4 a = __ldcs(&xv[i]);   // streaming loads: zero reuse
        const float4 b = __ldcs(&l0v[i]);
        const float4 c = __ldcs(&l1v[i]);
        const float4 d = __ldcs(&l2v[i]);
        __stcs(&outx[i], a);               // streaming store: never re-read

        s0 += DOT4(b, a);  // ly0 · x
        s1 += DOT4(c, a);  // ly1 · x
        s2 += DOT4(c, b);  // ly1 · ly0
        s3 += DOT4(d, a);  // ly2 · x
        s4 += DOT4(d, b);  // ly2 · ly0
        s5 += DOT4(d, c);  // ly2 · ly1
    }

    // Warp-level reduction
    #pragma unroll
    for (int off = 16; off > 0; off >>= 1) {
        s0 += __shfl_down_sync(0xFFFFFFFFu, s0, off);
        s1 += __shfl_down_sync(0xFFFFFFFFu, s1, off);
        s2 += __shfl_down_sync(0xFFFFFFFFu, s2, off);
        s3 += __shfl_down_sync(0xFFFFFFFFu, s3, off);
        s4 += __shfl_down_sync(0xFFFFFFFFu, s4, off);
        s5 += __shfl_down_sync(0xFFFFFFFFu, s5, off);
    }

    __shared__ float smem[6][NTHREADS / 32];
    __shared__ bool s_is_last;
    volatile __shared__ float s_old[6];  // forces atomic round-trip completion
    const int warp = threadIdx.x >> 5;
    const int lane = threadIdx.x & 31;
    if (lane == 0) {
        smem[0][warp] = s0; smem[1][warp] = s1; smem[2][warp] = s2;
        smem[3][warp] = s3; smem[4][warp] = s4; smem[5][warp] = s5;
    }
    __syncthreads();

    // Threads 0..5: atomicAdd into global accumulators; CONSUME the return
    // value so the atomic is performed at L2 before we pass the barrier.
    if (threadIdx.x < 6) {
        float v = 0.f;
        #pragma unroll
        for (int w = 0; w < NTHREADS / 32; w++) v += smem[threadIdx.x][w];
        float old = atomicAdd(&g_acc[threadIdx.x], v);
        s_old[threadIdx.x] = old;  // volatile STS: depends on atomic result
    }
    __syncthreads();  // drains STS; all 6 adds performed at L2 before ticket

    if (threadIdx.x == 0) {
        unsigned int t = atomicAdd(&g_ticket, 1u);
        s_is_last = (t == gridDim.x - 1);
    }
    __syncthreads();

    if (s_is_last) {
        // Every block's adds performed at L2 before its ticket; final ticket
        // observed => g_acc complete. Read + reset atomically.
        if (threadIdx.x < 6)
            out_tail[threadIdx.x] = atomicExch(&g_acc[threadIdx.x], 0.0f);
        if (threadIdx.x == 0)
            atomicExch(&g_ticket, 0u);  // reset for next graph replay
    }
}

extern "C" void kernel_launch(void* const* d_in, const int* in_sizes, int n_in,
                              void* d_out, int out_size) {
    const float* x  = (const float*)d_in[0];
    const float* l0 = (const float*)d_in[1];
    const float* l1 = (const float*)d_in[2];
    const float* l2 = (const float*)d_in[3];
    float* out = (float*)d_out;

    const int D  = in_sizes[0];   // 16777216
    const int n4 = D / 4;         // 4194304

    int blocks = NBLOCKS;
    const int maxBlocks = (n4 + NTHREADS - 1) / NTHREADS;
    if (blocks > maxBlocks) blocks = maxBlocks;

    dlrm_fused_kernel<<<blocks, NTHREADS>>>(
        (const float4*)x, (const float4*)l0, (const float4*)l1, (const float4*)l2,
        (float4*)out, out + D, n4);
}